// round 12
// baseline (speedup 1.0000x reference)
#include <cuda_runtime.h>
#include <math.h>

// Problem constants
#define D_MODEL   1024
#define MEM_HEADS 4
#define MEM_KNN   32
#define KEY_DIM   288
#define VALUE_DIM 512
#define Q_RANK    512
#define NUM_BUCKETS 18
#define BUCKET_DIM  16
#define NTOK      2048                        // BATCH * SEQ
#define NROWS     (NTOK * MEM_HEADS)          // 8192
#define NJ        (MEM_HEADS * NUM_BUCKETS * 2)  // 144 folded score columns
#define KSPLIT    4
#define NCHUNK2   2
#define CHTOK2    (NTOK / NCHUNK2)            // 1024

// Scratch (device globals; no allocation allowed)
__device__ float g_k2[NJ * Q_RANK];           // 288 KB
__device__ float g_w3[NJ * D_MODEL];          // 576 KB
__device__ float g_b2[NJ];
__device__ float g_spart[KSPLIT * NTOK * NJ]; // 4.7 MB
__device__ float g_scores[NROWS * MEM_KNN];   // 1 MB
__device__ int   g_indices[NROWS * MEM_KNN];  // 1 MB
__device__ float g_y[NTOK * VALUE_DIM];       // 4 MB

typedef union { unsigned long long u; float2 f; } pk_t;

// ---------------------------------------------------------------------------
// K2[j, r] = sum_d qu_w[h*288 + m*16 + d, r] * keys[h, m, c, d]
// ---------------------------------------------------------------------------
__global__ __launch_bounds__(256)
void build_k2(const float* __restrict__ qu_w, const float* __restrict__ keys,
              float* __restrict__ K2)
{
    int gid = blockIdx.x * blockDim.x + threadIdx.x;
    int r = gid & (Q_RANK - 1);
    int j = gid >> 9;
    if (j >= NJ) return;
    int c = j & 1;
    int m = (j >> 1) % NUM_BUCKETS;
    int h = j / (NUM_BUCKETS * 2);
    const float* kp = keys + (size_t)(((h * NUM_BUCKETS + m) * 2) + c) * BUCKET_DIM;
    const float* w  = qu_w + (size_t)(h * KEY_DIM + m * BUCKET_DIM) * Q_RANK + r;
    float s = 0.f;
    #pragma unroll
    for (int d = 0; d < BUCKET_DIM; d++)
        s += w[(size_t)d * Q_RANK] * kp[d];
    K2[(size_t)j * Q_RANK + r] = s;
}

// b2[j] = sum_r K2[j,r] * qd_b[r]
__global__ __launch_bounds__(32)
void build_b2(const float* __restrict__ K2, const float* __restrict__ qd_b,
              float* __restrict__ b2)
{
    int j = blockIdx.x;
    int lane = threadIdx.x;
    float s = 0.f;
    for (int r = lane; r < Q_RANK; r += 32)
        s += K2[(size_t)j * Q_RANK + r] * qd_b[r];
    #pragma unroll
    for (int o = 16; o >= 1; o >>= 1) s += __shfl_xor_sync(0xFFFFFFFFu, s, o);
    if (lane == 0) b2[j] = s;
}

// ---------------------------------------------------------------------------
// W3[j, d] = sum_r K2[j, r] * qd_w[r, d]   (NN GEMM: M=144, N=1024, K=512)
// ---------------------------------------------------------------------------
__global__ __launch_bounds__(256)
void build_w3(const float* __restrict__ K2, const float* __restrict__ qd_w,
              float* __restrict__ W3)
{
    __shared__ float K2s[16][17];
    __shared__ float Ws[16][64];
    int tid = threadIdx.x;
    int j0 = blockIdx.y * 16;
    int d0 = blockIdx.x * 64;
    int d  = tid & 63;
    int jg = tid >> 6;

    float acc[4] = {0.f, 0.f, 0.f, 0.f};
    for (int r0 = 0; r0 < Q_RANK; r0 += 16) {
        K2s[tid >> 4][tid & 15] = K2[(size_t)(j0 + (tid >> 4)) * Q_RANK + r0 + (tid & 15)];
        #pragma unroll
        for (int i = 0; i < 4; i++) {
            int e = tid + i * 256;
            Ws[e >> 6][e & 63] = qd_w[(size_t)(r0 + (e >> 6)) * D_MODEL + d0 + (e & 63)];
        }
        __syncthreads();
        #pragma unroll
        for (int r = 0; r < 16; r++) {
            float qv = Ws[r][d];
            #pragma unroll
            for (int i = 0; i < 4; i++)
                acc[i] += K2s[jg * 4 + i][r] * qv;
        }
        __syncthreads();
    }
    #pragma unroll
    for (int i = 0; i < 4; i++)
        W3[(size_t)(j0 + jg * 4 + i) * D_MODEL + d0 + d] = acc[i];
}

// ---------------------------------------------------------------------------
// Split-K score GEMM (f32x2): part[z] = x @ W3^T over K-chunk z.
// Tile 64x48, BK=16, 256 threads, per thread 2 M-packs x 3 cols.
// A packed over M-pairs from smem; B stored duplicated -> zero packing movs.
// ---------------------------------------------------------------------------
#define SBM 64
#define SBN 48
#define SBK 16
#define KCH (D_MODEL / KSPLIT)   // 256

__global__ __launch_bounds__(256)
void sgemm_s_splitk(const float* __restrict__ A, const float* __restrict__ B,
                    float* __restrict__ part)
{
    __shared__ __align__(16) float As[SBK][SBM + 4];
    __shared__ __align__(16) float Bd[SBK][2 * SBN + 4];

    const int tid = threadIdx.x;
    const int bn = blockIdx.x * SBN;
    const int bm = blockIdx.y * SBM;
    const int kz = blockIdx.z;
    const int tx = tid & 15;        // 3 cols
    const int ty = tid >> 4;        // 4 rows (2 packs)
    const int lr = tid >> 2;
    const int lk = (tid & 3) << 2;

    const float* Ap = A + (size_t)(bm + lr) * D_MODEL + kz * KCH + lk;
    const float* Bp = B + (size_t)(bn + lr) * D_MODEL + kz * KCH + lk;
    const bool bok = lr < SBN;

    unsigned long long acc[2][3];
    #pragma unroll
    for (int p = 0; p < 2; p++)
        #pragma unroll
        for (int j = 0; j < 3; j++) acc[p][j] = 0ULL;

    for (int k0 = 0; k0 < KCH; k0 += SBK) {
        float4 a = *(const float4*)(Ap + k0);
        As[lk + 0][lr] = a.x; As[lk + 1][lr] = a.y;
        As[lk + 2][lr] = a.z; As[lk + 3][lr] = a.w;
        if (bok) {
            float4 b = *(const float4*)(Bp + k0);
            *(float2*)&Bd[lk + 0][2 * lr] = make_float2(b.x, b.x);
            *(float2*)&Bd[lk + 1][2 * lr] = make_float2(b.y, b.y);
            *(float2*)&Bd[lk + 2][2 * lr] = make_float2(b.z, b.z);
            *(float2*)&Bd[lk + 3][2 * lr] = make_float2(b.w, b.w);
        }
        __syncthreads();
        #pragma unroll
        for (int kk = 0; kk < SBK; kk++) {
            ulonglong2 ap = *(const ulonglong2*)&As[kk][ty << 2];   // 2 M-packs
            unsigned long long b0 = *(const unsigned long long*)&Bd[kk][tx * 6 + 0];
            unsigned long long b1 = *(const unsigned long long*)&Bd[kk][tx * 6 + 2];
            unsigned long long b2 = *(const unsigned long long*)&Bd[kk][tx * 6 + 4];
            asm("fma.rn.f32x2 %0, %1, %2, %0;" : "+l"(acc[0][0]) : "l"(ap.x), "l"(b0));
            asm("fma.rn.f32x2 %0, %1, %2, %0;" : "+l"(acc[0][1]) : "l"(ap.x), "l"(b1));
            asm("fma.rn.f32x2 %0, %1, %2, %0;" : "+l"(acc[0][2]) : "l"(ap.x), "l"(b2));
            asm("fma.rn.f32x2 %0, %1, %2, %0;" : "+l"(acc[1][0]) : "l"(ap.y), "l"(b0));
            asm("fma.rn.f32x2 %0, %1, %2, %0;" : "+l"(acc[1][1]) : "l"(ap.y), "l"(b1));
            asm("fma.rn.f32x2 %0, %1, %2, %0;" : "+l"(acc[1][2]) : "l"(ap.y), "l"(b2));
        }
        __syncthreads();
    }

    float* P = part + (size_t)kz * NTOK * NJ;
    #pragma unroll
    for (int p = 0; p < 2; p++) {
        #pragma unroll
        for (int e = 0; e < 2; e++) {
            float* prow = P + (size_t)(bm + (ty << 2) + 2 * p + e) * NJ + bn + tx * 3;
            #pragma unroll
            for (int j = 0; j < 3; j++) {
                pk_t v; v.u = acc[p][j];
                prow[j] = e ? v.f.y : v.f.x;
            }
        }
    }
}

// ---------------------------------------------------------------------------
// Router (one warp per row): sums split-K partials + bias inline, then
// trellis top-32 + softmax.
// ---------------------------------------------------------------------------
__global__ __launch_bounds__(256)
void router_kernel(const float* __restrict__ part, const float* __restrict__ b2,
                   float* __restrict__ scores, int* __restrict__ indices)
{
    const unsigned FULL = 0xFFFFFFFFu;
    int warp = (blockIdx.x * blockDim.x + threadIdx.x) >> 5;
    int lane = threadIdx.x & 31;
    if (warp >= NROWS) return;

    int n = warp >> 2;
    int h = warp & 3;
    size_t base = (size_t)n * NJ + h * (NUM_BUCKETS * 2);

    float delta = 0.f, mx = 0.f;
    bool bb = false;
    if (lane < NUM_BUCKETS) {
        int j = lane * 2;
        float s0 = b2[h * (NUM_BUCKETS * 2) + j];
        float s1 = b2[h * (NUM_BUCKETS * 2) + j + 1];
        #pragma unroll
        for (int z = 0; z < KSPLIT; z++) {
            const float2 p = *(const float2*)&part[(size_t)z * NTOK * NJ + base + j];
            s0 += p.x;
            s1 += p.y;
        }
        bb = (s1 > s0);
        mx = fmaxf(s0, s1);
        delta = fabsf(s0 - s1);
    }

    unsigned code = __ballot_sync(FULL, bb) & 0x3FFFFu;
    float best = mx;
    #pragma unroll
    for (int o = 16; o >= 1; o >>= 1) best += __shfl_xor_sync(FULL, best, o);

    const float INF = __int_as_float(0x7f000000);
    float pen = (lane == 0) ? 0.f : INF;
    int   mask = 0;

    #pragma unroll
    for (int t = 0; t < NUM_BUCKETS; t++) {
        float dt = __shfl_sync(FULL, delta, t);
        int bit = 1 << t;
        float pr = __shfl_sync(FULL, pen, 31 - lane);
        int   mr = __shfl_sync(FULL, mask, 31 - lane);
        float pb = pr + dt;
        if (pb < pen) { pen = pb; mask = mr ^ bit; }
        #pragma unroll
        for (int st = 16; st >= 1; st >>= 1) {
            float p2 = __shfl_xor_sync(FULL, pen, st);
            int   m2 = __shfl_xor_sync(FULL, mask, st);
            bool lower = (lane & st) == 0;
            bool take = lower ? (p2 < pen) : (p2 > pen);
            if (take) { pen = p2; mask = m2; }
        }
    }

    float sc = best - pen;
    float m = sc;
    #pragma unroll
    for (int o = 16; o >= 1; o >>= 1) m = fmaxf(m, __shfl_xor_sync(FULL, m, o));
    float e = __expf(sc - m);
    float ssum = e;
    #pragma unroll
    for (int o = 16; o >= 1; o >>= 1) ssum += __shfl_xor_sync(FULL, ssum, o);

    scores[(size_t)warp * MEM_KNN + lane]  = e / ssum;
    indices[(size_t)warp * MEM_KNN + lane] = (int)code ^ mask;
}

// ---------------------------------------------------------------------------
// Gather + weighted sum: y[n,:] = sum_k score[n,k] * values[idx[n,k], :]
// ---------------------------------------------------------------------------
__global__ __launch_bounds__(128)
void gather_kernel(const float* __restrict__ values,
                   const float* __restrict__ scores,
                   const int* __restrict__ indices,
                   float* __restrict__ y)
{
    int n = blockIdx.x;
    int tid = threadIdx.x;
    __shared__ float sw[MEM_HEADS * MEM_KNN];
    __shared__ int   si[MEM_HEADS * MEM_KNN];
    sw[tid] = scores[(size_t)n * 128 + tid];
    si[tid] = indices[(size_t)n * 128 + tid];
    __syncthreads();

    const float4* V = (const float4*)values;
    float4 acc = make_float4(0.f, 0.f, 0.f, 0.f);
    #pragma unroll 4
    for (int k = 0; k < 128; k++) {
        float w = sw[k];
        long idx = si[k];
        float4 v = __ldg(&V[idx * (VALUE_DIM / 4) + tid]);
        acc.x += w * v.x; acc.y += w * v.y;
        acc.z += w * v.z; acc.w += w * v.w;
    }
    ((float4*)y)[(size_t)n * (VALUE_DIM / 4) + tid] = acc;
}

// ---------------------------------------------------------------------------
// f32x2 vp GEMM, mov-free inner loop: C[M,N] = A[M,K] @ B[N,K]^T
// 128x64 tile, BK=16, 256 threads, 4 M-packs x 4 cols per thread, dbl-buffered.
// A packed over M-pairs from smem; B stored duplicated in smem.
// ---------------------------------------------------------------------------
#define TBM 128
#define TBN 64
#define TBK 16

__global__ __launch_bounds__(256)
void sgemm_128x64_f2(const float* __restrict__ A, const float* __restrict__ B,
                     float* __restrict__ C, int N, int K)
{
    __shared__ __align__(16) float As[2][TBK][TBM + 4];
    __shared__ __align__(16) float Bd[2][TBK][2 * TBN + 4];

    const int tid = threadIdx.x;
    const int bm = blockIdx.y * TBM;
    const int bn = blockIdx.x * TBN;
    const int tx = tid & 15;      // 4 N cols
    const int ty = tid >> 4;      // 8 M rows = 4 packs

    const int alr = tid >> 1;           // 0..127
    const int alk = (tid & 1) << 3;     // 0 or 8
    const int blr = tid >> 2;           // 0..63
    const int blk = (tid & 3) << 2;     // 0,4,8,12

    const float* Ap = A + (size_t)(bm + alr) * K + alk;
    const float* Bp = B + (size_t)(bn + blr) * K + blk;

    unsigned long long acc[4][4];
    #pragma unroll
    for (int p = 0; p < 4; p++)
        #pragma unroll
        for (int j = 0; j < 4; j++) acc[p][j] = 0ULL;

    const int nk = K / TBK;

    {
        float4 a0 = *(const float4*)(Ap);
        float4 a1 = *(const float4*)(Ap + 4);
        float4 b0 = *(const float4*)(Bp);
        As[0][alk + 0][alr] = a0.x; As[0][alk + 1][alr] = a0.y;
        As[0][alk + 2][alr] = a0.z; As[0][alk + 3][alr] = a0.w;
        As[0][alk + 4][alr] = a1.x; As[0][alk + 5][alr] = a1.y;
        As[0][alk + 6][alr] = a1.z; As[0][alk + 7][alr] = a1.w;
        *(float2*)&Bd[0][blk + 0][2 * blr] = make_float2(b0.x, b0.x);
        *(float2*)&Bd[0][blk + 1][2 * blr] = make_float2(b0.y, b0.y);
        *(float2*)&Bd[0][blk + 2][2 * blr] = make_float2(b0.z, b0.z);
        *(float2*)&Bd[0][blk + 3][2 * blr] = make_float2(b0.w, b0.w);
    }
    __syncthreads();

    for (int t = 0; t < nk; t++) {
        const int cur = t & 1;
        float4 a0, a1, b0;
        const bool has = (t + 1 < nk);
        if (has) {
            const float* Ap2 = Ap + (t + 1) * TBK;
            a0 = *(const float4*)(Ap2);
            a1 = *(const float4*)(Ap2 + 4);
            b0 = *(const float4*)(Bp + (t + 1) * TBK);
        }

        #pragma unroll
        for (int kk = 0; kk < TBK; kk++) {
            ulonglong2 apl = *(const ulonglong2*)&As[cur][kk][ty << 3];        // packs 0,1
            ulonglong2 aph = *(const ulonglong2*)&As[cur][kk][(ty << 3) + 4];  // packs 2,3
            ulonglong2 bdl = *(const ulonglong2*)&Bd[cur][kk][tx << 3];        // dup cols 0,1
            ulonglong2 bdh = *(const ulonglong2*)&Bd[cur][kk][(tx << 3) + 4];  // dup cols 2,3
            unsigned long long ap[4] = {apl.x, apl.y, aph.x, aph.y};
            unsigned long long bd[4] = {bdl.x, bdl.y, bdh.x, bdh.y};
            #pragma unroll
            for (int p = 0; p < 4; p++)
                #pragma unroll
                for (int j = 0; j < 4; j++)
                    asm("fma.rn.f32x2 %0, %1, %2, %0;"
                        : "+l"(acc[p][j]) : "l"(ap[p]), "l"(bd[j]));
        }

        if (has) {
            const int nxt = cur ^ 1;
            As[nxt][alk + 0][alr] = a0.x; As[nxt][alk + 1][alr] = a0.y;
            As[nxt][alk + 2][alr] = a0.z; As[nxt][alk + 3][alr] = a0.w;
            As[nxt][alk + 4][alr] = a1.x; As[nxt][alk + 5][alr] = a1.y;
            As[nxt][alk + 6][alr] = a1.z; As[nxt][alk + 7][alr] = a1.w;
            *(float2*)&Bd[nxt][blk + 0][2 * blr] = make_float2(b0.x, b0.x);
            *(float2*)&Bd[nxt][blk + 1][2 * blr] = make_float2(b0.y, b0.y);
            *(float2*)&Bd[nxt][blk + 2][2 * blr] = make_float2(b0.z, b0.z);
            *(float2*)&Bd[nxt][blk + 3][2 * blr] = make_float2(b0.w, b0.w);
        }
        __syncthreads();
    }

    #pragma unroll
    for (int p = 0; p < 4; p++) {
        #pragma unroll
        for (int e = 0; e < 2; e++) {
            pk_t v0, v1, v2, v3;
            v0.u = acc[p][0]; v1.u = acc[p][1];
            v2.u = acc[p][2]; v3.u = acc[p][3];
            float4 out = e ? make_float4(v0.f.y, v1.f.y, v2.f.y, v3.f.y)
                           : make_float4(v0.f.x, v1.f.x, v2.f.x, v3.f.x);
            float* crow = C + (size_t)(bm + (ty << 3) + 2 * p + e) * N + bn + (tx << 2);
            *(float4*)crow = out;
        }
    }
}

// ---------------------------------------------------------------------------
struct AuxRes {
    cudaStream_t s2;
    cudaEvent_t evR;
    cudaEvent_t evG[NCHUNK2];
    AuxRes() {
        cudaStreamCreate(&s2);
        cudaEventCreateWithFlags(&evR, cudaEventDisableTiming);
        for (int i = 0; i < NCHUNK2; i++)
            cudaEventCreateWithFlags(&evG[i], cudaEventDisableTiming);
    }
};

extern "C" void kernel_launch(void* const* d_in, const int* in_sizes, int n_in,
                              void* d_out, int out_size)
{
    const float* x      = (const float*)d_in[0];   // [2048,1024]
    const float* keys   = (const float*)d_in[1];   // [4,18,2,16]
    const float* qd_w   = (const float*)d_in[2];   // [512,1024]
    const float* qd_b   = (const float*)d_in[3];   // [512]
    const float* qu_w   = (const float*)d_in[4];   // [1152,512]
    const float* values = (const float*)d_in[5];   // [262144,512]
    const float* vp_w   = (const float*)d_in[6];   // [1024,512]
    float* out = (float*)d_out;                    // [2048,1024]

    static AuxRes aux;

    float *k2, *w3, *b2, *spart, *sc, *y;
    int *idx;
    cudaGetSymbolAddress((void**)&k2,    g_k2);
    cudaGetSymbolAddress((void**)&w3,    g_w3);
    cudaGetSymbolAddress((void**)&b2,    g_b2);
    cudaGetSymbolAddress((void**)&spart, g_spart);
    cudaGetSymbolAddress((void**)&sc,    g_scores);
    cudaGetSymbolAddress((void**)&idx,   g_indices);
    cudaGetSymbolAddress((void**)&y,     g_y);

    // Fold qu_w through keys: K2 [144, 512]
    build_k2<<<(NJ * Q_RANK) / 256, 256>>>(qu_w, keys, k2);
    // b2 [144]
    build_b2<<<NJ, 32>>>(k2, qd_b, b2);
    // W3 [144, 1024]
    build_w3<<<dim3(D_MODEL / 64, NJ / 16), 256>>>(k2, qd_w, w3);
    // score partials: x @ W3^T, split-K (f32x2)
    sgemm_s_splitk<<<dim3(NJ / SBN, NTOK / SBM, KSPLIT), 256>>>(x, w3, spart);
    // router: partial-sum + bias + trellis + softmax
    router_kernel<<<(NROWS * 32) / 256, 256>>>(spart, b2, sc, idx);

    // Gather (stream s2, 2 chunks) overlapped with vp GEMM (default stream).
    // Each vp chunk is 128 CTAs = one full wave; chunking adds no extra waves.
    cudaEventRecord(aux.evR, 0);
    cudaStreamWaitEvent(aux.s2, aux.evR, 0);
    for (int c = 0; c < NCHUNK2; c++) {
        gather_kernel<<<CHTOK2, 128, 0, aux.s2>>>(
            values,
            sc  + (size_t)c * CHTOK2 * (MEM_HEADS * MEM_KNN),
            idx + (size_t)c * CHTOK2 * (MEM_HEADS * MEM_KNN),
            y   + (size_t)c * CHTOK2 * VALUE_DIM);
        cudaEventRecord(aux.evG[c], aux.s2);
    }
    for (int c = 0; c < NCHUNK2; c++) {
        cudaStreamWaitEvent(0, aux.evG[c], 0);
        sgemm_128x64_f2<<<dim3(D_MODEL / TBN, CHTOK2 / TBM), 256>>>(
            y   + (size_t)c * CHTOK2 * VALUE_DIM,
            vp_w,
            out + (size_t)c * CHTOK2 * D_MODEL,
            D_MODEL, VALUE_DIM);
    }
}

// round 16
// speedup vs baseline: 1.5042x; 1.5042x over previous
#include <cuda_runtime.h>
#include <math.h>

// Problem constants
#define D_MODEL   1024
#define MEM_HEADS 4
#define MEM_KNN   32
#define KEY_DIM   288
#define VALUE_DIM 512
#define Q_RANK    512
#define NUM_BUCKETS 18
#define BUCKET_DIM  16
#define NTOK      2048                        // BATCH * SEQ
#define NROWS     (NTOK * MEM_HEADS)          // 8192
#define NJ        (MEM_HEADS * NUM_BUCKETS * 2)  // 144 folded score columns
#define KSPLIT    8

// Scratch (device globals; no allocation allowed)
__device__ float g_k2[NJ * Q_RANK];           // 288 KB
__device__ float g_w3[NJ * D_MODEL];          // 576 KB
__device__ float g_b2[NJ];
__device__ float g_spart[KSPLIT * NTOK * NJ]; // 9.4 MB
__device__ float g_scores[NROWS * MEM_KNN];   // 1 MB
__device__ int   g_indices[NROWS * MEM_KNN];  // 1 MB
__device__ float g_y[NTOK * VALUE_DIM];       // 4 MB

// ---------------------------------------------------------------------------
// K2[j, r] = sum_d qu_w[h*288 + m*16 + d, r] * keys[h, m, c, d]
// ---------------------------------------------------------------------------
__global__ __launch_bounds__(256)
void build_k2(const float* __restrict__ qu_w, const float* __restrict__ keys,
              float* __restrict__ K2)
{
    int gid = blockIdx.x * blockDim.x + threadIdx.x;
    int r = gid & (Q_RANK - 1);
    int j = gid >> 9;
    if (j >= NJ) return;
    int c = j & 1;
    int m = (j >> 1) % NUM_BUCKETS;
    int h = j / (NUM_BUCKETS * 2);
    const float* kp = keys + (size_t)(((h * NUM_BUCKETS + m) * 2) + c) * BUCKET_DIM;
    const float* w  = qu_w + (size_t)(h * KEY_DIM + m * BUCKET_DIM) * Q_RANK + r;
    float s = 0.f;
    #pragma unroll
    for (int d = 0; d < BUCKET_DIM; d++)
        s += w[(size_t)d * Q_RANK] * kp[d];
    K2[(size_t)j * Q_RANK + r] = s;
}

// b2[j] = sum_r K2[j,r] * qd_b[r]
__global__ __launch_bounds__(32)
void build_b2(const float* __restrict__ K2, const float* __restrict__ qd_b,
              float* __restrict__ b2)
{
    int j = blockIdx.x;
    int lane = threadIdx.x;
    float s = 0.f;
    for (int r = lane; r < Q_RANK; r += 32)
        s += K2[(size_t)j * Q_RANK + r] * qd_b[r];
    #pragma unroll
    for (int o = 16; o >= 1; o >>= 1) s += __shfl_xor_sync(0xFFFFFFFFu, s, o);
    if (lane == 0) b2[j] = s;
}

// ---------------------------------------------------------------------------
// W3[j, d] = sum_r K2[j, r] * qd_w[r, d]   (NN GEMM: M=144, N=1024, K=512)
// ---------------------------------------------------------------------------
__global__ __launch_bounds__(256)
void build_w3(const float* __restrict__ K2, const float* __restrict__ qd_w,
              float* __restrict__ W3)
{
    __shared__ float K2s[16][17];
    __shared__ float Ws[16][64];
    int tid = threadIdx.x;
    int j0 = blockIdx.y * 16;
    int d0 = blockIdx.x * 64;
    int d  = tid & 63;
    int jg = tid >> 6;

    float acc[4] = {0.f, 0.f, 0.f, 0.f};
    for (int r0 = 0; r0 < Q_RANK; r0 += 16) {
        K2s[tid >> 4][tid & 15] = K2[(size_t)(j0 + (tid >> 4)) * Q_RANK + r0 + (tid & 15)];
        #pragma unroll
        for (int i = 0; i < 4; i++) {
            int e = tid + i * 256;
            Ws[e >> 6][e & 63] = qd_w[(size_t)(r0 + (e >> 6)) * D_MODEL + d0 + (e & 63)];
        }
        __syncthreads();
        #pragma unroll
        for (int r = 0; r < 16; r++) {
            float qv = Ws[r][d];
            #pragma unroll
            for (int i = 0; i < 4; i++)
                acc[i] += K2s[jg * 4 + i][r] * qv;
        }
        __syncthreads();
    }
    #pragma unroll
    for (int i = 0; i < 4; i++)
        W3[(size_t)(j0 + jg * 4 + i) * D_MODEL + d0 + d] = acc[i];
}

// ---------------------------------------------------------------------------
// Split-K score GEMM (scalar, R6 form): part[z] = x @ W3^T over K-chunk z.
// Tile 64x48, BK=16, 256 threads, 4x3 per thread. Grid (3, 32, KSPLIT).
// ---------------------------------------------------------------------------
#define SBM 64
#define SBN 48
#define SBK 16
#define KCH (D_MODEL / KSPLIT)   // 128

__global__ __launch_bounds__(256)
void sgemm_s_splitk(const float* __restrict__ A, const float* __restrict__ B,
                    float* __restrict__ part)
{
    __shared__ float As[SBK][SBM + 4];
    __shared__ float Bs[SBK][SBN + 1];

    const int tid = threadIdx.x;
    const int bn = blockIdx.x * SBN;
    const int bm = blockIdx.y * SBM;
    const int kz = blockIdx.z;
    const int tx = tid & 15;        // 3 cols
    const int ty = tid >> 4;        // 4 rows
    const int lr = tid >> 2;
    const int lk = (tid & 3) << 2;

    const float* Ap = A + (size_t)(bm + lr) * D_MODEL + kz * KCH + lk;
    const float* Bp = B + (size_t)(bn + lr) * D_MODEL + kz * KCH + lk;
    const bool bok = lr < SBN;

    float acc[4][3];
    #pragma unroll
    for (int i = 0; i < 4; i++)
        #pragma unroll
        for (int j = 0; j < 3; j++) acc[i][j] = 0.f;

    for (int k0 = 0; k0 < KCH; k0 += SBK) {
        float4 a = *(const float4*)(Ap + k0);
        As[lk + 0][lr] = a.x; As[lk + 1][lr] = a.y;
        As[lk + 2][lr] = a.z; As[lk + 3][lr] = a.w;
        if (bok) {
            float4 b = *(const float4*)(Bp + k0);
            Bs[lk + 0][lr] = b.x; Bs[lk + 1][lr] = b.y;
            Bs[lk + 2][lr] = b.z; Bs[lk + 3][lr] = b.w;
        }
        __syncthreads();
        #pragma unroll
        for (int kk = 0; kk < SBK; kk++) {
            float4 ar = *(const float4*)&As[kk][ty << 2];
            float a0[4] = {ar.x, ar.y, ar.z, ar.w};
            float b0 = Bs[kk][tx * 3 + 0];
            float b1 = Bs[kk][tx * 3 + 1];
            float b2 = Bs[kk][tx * 3 + 2];
            #pragma unroll
            for (int i = 0; i < 4; i++) {
                acc[i][0] += a0[i] * b0;
                acc[i][1] += a0[i] * b1;
                acc[i][2] += a0[i] * b2;
            }
        }
        __syncthreads();
    }

    float* P = part + (size_t)kz * NTOK * NJ;
    #pragma unroll
    for (int i = 0; i < 4; i++) {
        float* prow = P + (size_t)(bm + (ty << 2) + i) * NJ + bn + tx * 3;
        #pragma unroll
        for (int j = 0; j < 3; j++) prow[j] = acc[i][j];
    }
}

// ---------------------------------------------------------------------------
// Router (one warp per row): sums split-K partials + bias inline, then
// trellis top-32 + softmax.
// ---------------------------------------------------------------------------
__global__ __launch_bounds__(256)
void router_kernel(const float* __restrict__ part, const float* __restrict__ b2,
                   float* __restrict__ scores, int* __restrict__ indices)
{
    const unsigned FULL = 0xFFFFFFFFu;
    int warp = (blockIdx.x * blockDim.x + threadIdx.x) >> 5;
    int lane = threadIdx.x & 31;
    if (warp >= NROWS) return;

    int n = warp >> 2;
    int h = warp & 3;
    size_t base = (size_t)n * NJ + h * (NUM_BUCKETS * 2);

    float delta = 0.f, mx = 0.f;
    bool bb = false;
    if (lane < NUM_BUCKETS) {
        int j = lane * 2;
        float s0 = b2[h * (NUM_BUCKETS * 2) + j];
        float s1 = b2[h * (NUM_BUCKETS * 2) + j + 1];
        #pragma unroll
        for (int z = 0; z < KSPLIT; z++) {
            const float2 p = *(const float2*)&part[(size_t)z * NTOK * NJ + base + j];
            s0 += p.x;
            s1 += p.y;
        }
        bb = (s1 > s0);
        mx = fmaxf(s0, s1);
        delta = fabsf(s0 - s1);
    }

    unsigned code = __ballot_sync(FULL, bb) & 0x3FFFFu;
    float best = mx;
    #pragma unroll
    for (int o = 16; o >= 1; o >>= 1) best += __shfl_xor_sync(FULL, best, o);

    const float INF = __int_as_float(0x7f000000);
    float pen = (lane == 0) ? 0.f : INF;
    int   mask = 0;

    #pragma unroll
    for (int t = 0; t < NUM_BUCKETS; t++) {
        float dt = __shfl_sync(FULL, delta, t);
        int bit = 1 << t;
        float pr = __shfl_sync(FULL, pen, 31 - lane);
        int   mr = __shfl_sync(FULL, mask, 31 - lane);
        float pb = pr + dt;
        if (pb < pen) { pen = pb; mask = mr ^ bit; }
        #pragma unroll
        for (int st = 16; st >= 1; st >>= 1) {
            float p2 = __shfl_xor_sync(FULL, pen, st);
            int   m2 = __shfl_xor_sync(FULL, mask, st);
            bool lower = (lane & st) == 0;
            bool take = lower ? (p2 < pen) : (p2 > pen);
            if (take) { pen = p2; mask = m2; }
        }
    }

    float sc = best - pen;
    float m = sc;
    #pragma unroll
    for (int o = 16; o >= 1; o >>= 1) m = fmaxf(m, __shfl_xor_sync(FULL, m, o));
    float e = __expf(sc - m);
    float ssum = e;
    #pragma unroll
    for (int o = 16; o >= 1; o >>= 1) ssum += __shfl_xor_sync(FULL, ssum, o);

    scores[(size_t)warp * MEM_KNN + lane]  = e / ssum;
    indices[(size_t)warp * MEM_KNN + lane] = (int)code ^ mask;
}

// ---------------------------------------------------------------------------
// Gather + weighted sum: y[n,:] = sum_k score[n,k] * values[idx[n,k], :]
// ---------------------------------------------------------------------------
__global__ __launch_bounds__(128)
void gather_kernel(const float* __restrict__ values,
                   const float* __restrict__ scores,
                   const int* __restrict__ indices,
                   float* __restrict__ y)
{
    int n = blockIdx.x;
    int tid = threadIdx.x;
    __shared__ float sw[MEM_HEADS * MEM_KNN];
    __shared__ int   si[MEM_HEADS * MEM_KNN];
    sw[tid] = scores[(size_t)n * 128 + tid];
    si[tid] = indices[(size_t)n * 128 + tid];
    __syncthreads();

    const float4* V = (const float4*)values;
    float4 acc = make_float4(0.f, 0.f, 0.f, 0.f);
    #pragma unroll 4
    for (int k = 0; k < 128; k++) {
        float w = sw[k];
        long idx = si[k];
        float4 v = __ldg(&V[idx * (VALUE_DIM / 4) + tid]);
        acc.x += w * v.x; acc.y += w * v.y;
        acc.z += w * v.z; acc.w += w * v.w;
    }
    ((float4*)y)[(size_t)n * (VALUE_DIM / 4) + tid] = acc;
}

// ---------------------------------------------------------------------------
// f32x2 vp GEMM (R6 form, measured good): C[M,N] = A[M,K] @ B[N,K]^T
// 128x64 tile, BK=16, 256 threads, 8x4 per thread (as 8x2 f32x2), dbl-buffered.
// ---------------------------------------------------------------------------
#define TBM 128
#define TBN 64
#define TBK 16

__global__ __launch_bounds__(256)
void sgemm_128x64_f2(const float* __restrict__ A, const float* __restrict__ B,
                     float* __restrict__ C, int N, int K)
{
    __shared__ float As[2][TBK][TBM + 4];
    __shared__ float Bs[2][TBK][TBN + 4];

    const int tid = threadIdx.x;
    const int bm = blockIdx.y * TBM;
    const int bn = blockIdx.x * TBN;
    const int tx = tid & 15;      // N: 4 cols (2 f32x2)
    const int ty = tid >> 4;      // M: 8 rows

    const int alr = tid >> 1;
    const int alk = (tid & 1) << 3;
    const int blr = tid >> 2;
    const int blk = (tid & 3) << 2;

    const float* Ap = A + (size_t)(bm + alr) * K + alk;
    const float* Bp = B + (size_t)(bn + blr) * K + blk;

    unsigned long long acc[8][2];
    #pragma unroll
    for (int i = 0; i < 8; i++) { acc[i][0] = 0ULL; acc[i][1] = 0ULL; }

    const int nk = K / TBK;

    {
        float4 a0 = *(const float4*)(Ap);
        float4 a1 = *(const float4*)(Ap + 4);
        float4 b0 = *(const float4*)(Bp);
        As[0][alk + 0][alr] = a0.x; As[0][alk + 1][alr] = a0.y;
        As[0][alk + 2][alr] = a0.z; As[0][alk + 3][alr] = a0.w;
        As[0][alk + 4][alr] = a1.x; As[0][alk + 5][alr] = a1.y;
        As[0][alk + 6][alr] = a1.z; As[0][alk + 7][alr] = a1.w;
        Bs[0][blk + 0][blr] = b0.x; Bs[0][blk + 1][blr] = b0.y;
        Bs[0][blk + 2][blr] = b0.z; Bs[0][blk + 3][blr] = b0.w;
    }
    __syncthreads();

    for (int t = 0; t < nk; t++) {
        const int cur = t & 1;
        float4 a0, a1, b0;
        const bool has = (t + 1 < nk);
        if (has) {
            const float* Ap2 = Ap + (t + 1) * TBK;
            a0 = *(const float4*)(Ap2);
            a1 = *(const float4*)(Ap2 + 4);
            b0 = *(const float4*)(Bp + (t + 1) * TBK);
        }

        #pragma unroll
        for (int kk = 0; kk < TBK; kk++) {
            float4 ar0 = *(const float4*)&As[cur][kk][ty << 3];
            float4 ar1 = *(const float4*)&As[cur][kk][(ty << 3) + 4];
            ulonglong2 bd = *(const ulonglong2*)&Bs[cur][kk][tx << 2];
            float av[8] = {ar0.x, ar0.y, ar0.z, ar0.w, ar1.x, ar1.y, ar1.z, ar1.w};
            #pragma unroll
            for (int i = 0; i < 8; i++) {
                unsigned long long a2;
                asm("mov.b64 %0, {%1, %1};" : "=l"(a2) : "f"(av[i]));
                asm("fma.rn.f32x2 %0, %1, %2, %0;" : "+l"(acc[i][0]) : "l"(a2), "l"(bd.x));
                asm("fma.rn.f32x2 %0, %1, %2, %0;" : "+l"(acc[i][1]) : "l"(a2), "l"(bd.y));
            }
        }

        if (has) {
            const int nxt = cur ^ 1;
            As[nxt][alk + 0][alr] = a0.x; As[nxt][alk + 1][alr] = a0.y;
            As[nxt][alk + 2][alr] = a0.z; As[nxt][alk + 3][alr] = a0.w;
            As[nxt][alk + 4][alr] = a1.x; As[nxt][alk + 5][alr] = a1.y;
            As[nxt][alk + 6][alr] = a1.z; As[nxt][alk + 7][alr] = a1.w;
            Bs[nxt][blk + 0][blr] = b0.x; Bs[nxt][blk + 1][blr] = b0.y;
            Bs[nxt][blk + 2][blr] = b0.z; Bs[nxt][blk + 3][blr] = b0.w;
        }
        __syncthreads();
    }

    #pragma unroll
    for (int i = 0; i < 8; i++) {
        float c0, c1, c2, c3;
        asm("mov.b64 {%0, %1}, %2;" : "=f"(c0), "=f"(c1) : "l"(acc[i][0]));
        asm("mov.b64 {%0, %1}, %2;" : "=f"(c2), "=f"(c3) : "l"(acc[i][1]));
        float* crow = C + (size_t)(bm + (ty << 3) + i) * N + bn + (tx << 2);
        *(float4*)crow = make_float4(c0, c1, c2, c3);
    }
}

// ---------------------------------------------------------------------------
extern "C" void kernel_launch(void* const* d_in, const int* in_sizes, int n_in,
                              void* d_out, int out_size)
{
    const float* x      = (const float*)d_in[0];   // [2048,1024]
    const float* keys   = (const float*)d_in[1];   // [4,18,2,16]
    const float* qd_w   = (const float*)d_in[2];   // [512,1024]
    const float* qd_b   = (const float*)d_in[3];   // [512]
    const float* qu_w   = (const float*)d_in[4];   // [1152,512]
    const float* values = (const float*)d_in[5];   // [262144,512]
    const float* vp_w   = (const float*)d_in[6];   // [1024,512]
    float* out = (float*)d_out;                    // [2048,1024]

    float *k2, *w3, *b2, *spart, *sc, *y;
    int *idx;
    cudaGetSymbolAddress((void**)&k2,    g_k2);
    cudaGetSymbolAddress((void**)&w3,    g_w3);
    cudaGetSymbolAddress((void**)&b2,    g_b2);
    cudaGetSymbolAddress((void**)&spart, g_spart);
    cudaGetSymbolAddress((void**)&sc,    g_scores);
    cudaGetSymbolAddress((void**)&idx,   g_indices);
    cudaGetSymbolAddress((void**)&y,     g_y);

    // Fold qu_w through keys: K2 [144, 512]
    build_k2<<<(NJ * Q_RANK) / 256, 256>>>(qu_w, keys, k2);
    // b2 [144]
    build_b2<<<NJ, 32>>>(k2, qd_b, b2);
    // W3 [144, 1024]
    build_w3<<<dim3(D_MODEL / 64, NJ / 16), 256>>>(k2, qd_w, w3);
    // score partials: x @ W3^T, split-K (KSPLIT=8 -> 768 CTAs)
    sgemm_s_splitk<<<dim3(NJ / SBN, NTOK / SBM, KSPLIT), 256>>>(x, w3, spart);
    // router: partial-sum + bias + trellis + softmax
    router_kernel<<<(NROWS * 32) / 256, 256>>>(spart, b2, sc, idx);
    // gather + weighted sum [2048,512]
    gather_kernel<<<NTOK, 128>>>(values, sc, idx, y);
    // value proj: out = y @ vp_w^T [2048,1024]
    sgemm_128x64_f2<<<dim3(D_MODEL / TBN, NTOK / TBM), 256>>>(
        y, vp_w, out, D_MODEL, VALUE_DIM);
}